// round 17
// baseline (speedup 1.0000x reference)
#include <cuda_runtime.h>
#include <cstdint>

#define B_    256
#define NA    196
#define NB    196
#define DK    256
#define DIM   1024
#define SMOOTH 4.0f

// Scratch: attn TRANSPOSED: [B, NB, NA] fp32
__device__ float g_attn[(size_t)B_ * NB * NA];

__device__ __forceinline__ uint32_t f2tf32(float x) {
    uint32_t u;
    asm("cvt.rna.tf32.f32 %0, %1;" : "=r"(u) : "f"(x));
    return u;
}
__device__ __forceinline__ float tf32f(float x) {
    return __uint_as_float(f2tf32(x));
}
__device__ __forceinline__ float4 tf32x4(float4 v) {
    v.x = tf32f(v.x); v.y = tf32f(v.y); v.z = tf32f(v.z); v.w = tf32f(v.w);
    return v;
}
__device__ __forceinline__ void mma_tf32(float* d,
                                         uint32_t a0, uint32_t a1, uint32_t a2, uint32_t a3,
                                         uint32_t b0, uint32_t b1) {
    asm volatile(
        "mma.sync.aligned.m16n8k8.row.col.f32.tf32.tf32.f32 "
        "{%0,%1,%2,%3}, {%4,%5,%6,%7}, {%8,%9}, {%10,%11,%12,%13};\n"
        : "=f"(d[0]), "=f"(d[1]), "=f"(d[2]), "=f"(d[3])
        : "r"(a0), "r"(a1), "r"(a2), "r"(a3), "r"(b0), "r"(b1),
          "f"(d[0]), "f"(d[1]), "f"(d[2]), "f"(d[3]));
}
__device__ __forceinline__ uint32_t smem_u32(const void* p) {
    return (uint32_t)__cvta_generic_to_shared(p);
}
__device__ __forceinline__ void ldsm_x4(uint32_t& r0, uint32_t& r1,
                                        uint32_t& r2, uint32_t& r3, uint32_t a) {
    asm volatile("ldmatrix.sync.aligned.m8n8.x4.shared.b16 {%0,%1,%2,%3}, [%4];"
                 : "=r"(r0), "=r"(r1), "=r"(r2), "=r"(r3) : "r"(a));
}
__device__ __forceinline__ void ldsm_x2(uint32_t& r0, uint32_t& r1, uint32_t a) {
    asm volatile("ldmatrix.sync.aligned.m8n8.x2.shared.b16 {%0,%1}, [%2];"
                 : "=r"(r0), "=r"(r1) : "r"(a));
}
__device__ __forceinline__ void cp_async16(uint32_t dst, const void* src, bool pred) {
    int sz = pred ? 16 : 0;
    asm volatile("cp.async.cg.shared.global [%0], [%1], 16, %2;"
                 :: "r"(dst), "l"(src), "r"(sz) : "memory");
}
__device__ __forceinline__ void cp_commit() {
    asm volatile("cp.async.commit_group;" ::: "memory");
}
template <int N>
__device__ __forceinline__ void cp_wait() {
    asm volatile("cp.async.wait_group %0;" :: "n"(N) : "memory");
}

// ---------------------------------------------------------------------------
// Kernel 1 (3xTF32 mma.sync + ldmatrix): energy = Q @ K, fused softmax,
// writes attn TRANSPOSED g_attn[b][n][a].   (unchanged — passing at R12)
// ---------------------------------------------------------------------------
#define K1_MT   32
#define K1_NT   224
#define K1_PAD  20
#define K1_EPAD 228
#define K1_CH   16          // DK / 16

#define K1_AS_BUF  1280
#define K1_AS_HL   640
#define K1_BS_OFF  2560
#define K1_BS_BUF  8960
#define K1_BS_HL   4480
#define K1_SMEM_BYTES 81920

__global__ __launch_bounds__(256) void energy_softmax_mma_kernel(
    const float* __restrict__ Q,   // [B, NA, DK]
    const float* __restrict__ K)   // [B, DK, NB]
{
    extern __shared__ __align__(16) float sm[];
    float* As = sm;
    float* Bs = sm + K1_BS_OFF;
    float* E  = sm;

    const int tid  = threadIdx.x;
    const int wid  = tid >> 5;
    const int lane = tid & 31;

    const int b  = blockIdx.y;
    const int a0 = blockIdx.x * K1_MT;

    const float* Qb = Q + (size_t)b * NA * DK;
    const float* Kb = K + (size_t)b * DK * NB;

    const int warp_m = (wid >> 2) * 16;
    const int warp_n = (wid & 3) * 56;

    const int lm_hi = (lane >> 3) & 1;
    const int lm_q  = lane >> 4;
    const int lm_r  = lane & 7;
    const uint32_t smBase = smem_u32(sm);
    const uint32_t a_off = (uint32_t)((warp_m + lm_hi * 8 + lm_r) * K1_PAD * 4 + lm_q * 16);
    const uint32_t b_off = (uint32_t)((warp_n + lm_q * 8 + lm_r) * K1_PAD * 4 + lm_hi * 16);

    float c[7][4];
#pragma unroll
    for (int j = 0; j < 7; j++)
#pragma unroll
        for (int i = 0; i < 4; i++) c[j][i] = 0.f;

    const int a_row = tid >> 2;
    const int a_c4  = tid & 3;
    const bool a_act = (tid < 128);
    const bool a_val = a_act && (a0 + a_row < NA);
    const bool b_act = (tid < K1_NT);
    const bool b_val = b_act && (tid < NB);

    float4 av;
    float bv[16];

    auto ldg_chunk = [&](int kb) {
        const int kbase = kb * 16;
        if (a_act) {
            av = make_float4(0.f, 0.f, 0.f, 0.f);
            if (a_val)
                av = *(const float4*)(Qb + (size_t)(a0 + a_row) * DK + kbase + a_c4 * 4);
        }
        if (b_act) {
#pragma unroll
            for (int kk = 0; kk < 16; kk++)
                bv[kk] = b_val ? Kb[(size_t)(kbase + kk) * NB + tid] : 0.f;
        }
    };
    auto sts_chunk = [&](int buf) {
        if (a_act) {
            float4 hi = tf32x4(av);
            float4 lo = make_float4(av.x - hi.x, av.y - hi.y, av.z - hi.z, av.w - hi.w);
            lo = tf32x4(lo);
            float* dstH = As + buf * K1_AS_BUF + a_row * K1_PAD + a_c4 * 4;
            *(float4*)dstH = hi;
            *(float4*)(dstH + K1_AS_HL) = lo;
        }
        if (b_act) {
            float* browH = Bs + buf * K1_BS_BUF + tid * K1_PAD;
#pragma unroll
            for (int g4 = 0; g4 < 4; g4++) {
                float4 v = make_float4(bv[g4 * 4], bv[g4 * 4 + 1], bv[g4 * 4 + 2], bv[g4 * 4 + 3]);
                float4 hi = tf32x4(v);
                float4 lo = make_float4(v.x - hi.x, v.y - hi.y, v.z - hi.z, v.w - hi.w);
                lo = tf32x4(lo);
                *(float4*)(browH + g4 * 4) = hi;
                *(float4*)(browH + K1_BS_HL + g4 * 4) = lo;
            }
        }
    };

    ldg_chunk(0);
    sts_chunk(0);
    __syncthreads();

    for (int kb = 0; kb < K1_CH; kb++) {
        const int buf = kb & 1;
        if (kb + 1 < K1_CH) ldg_chunk(kb + 1);

        const uint32_t aH = smBase + (buf * K1_AS_BUF) * 4 + a_off;
        const uint32_t aL = aH + K1_AS_HL * 4;
        const uint32_t bH = smBase + (K1_BS_OFF + buf * K1_BS_BUF) * 4 + b_off;
        const uint32_t bL = bH + K1_BS_HL * 4;

#pragma unroll
        for (int s = 0; s < 2; s++) {
            uint32_t ah0, ah1, ah2, ah3, al0, al1, al2, al3;
            ldsm_x4(ah0, ah1, ah2, ah3, aH + s * 32);
            ldsm_x4(al0, al1, al2, al3, aL + s * 32);
#pragma unroll
            for (int jp = 0; jp < 3; jp++) {
                uint32_t bh0, bh1, bh2, bh3, bl0, bl1, bl2, bl3;
                ldsm_x4(bh0, bh1, bh2, bh3, bH + jp * 1280 + s * 32);
                ldsm_x4(bl0, bl1, bl2, bl3, bL + jp * 1280 + s * 32);
                mma_tf32(c[2 * jp],     ah0, ah1, ah2, ah3, bl0, bl1);
                mma_tf32(c[2 * jp],     al0, al1, al2, al3, bh0, bh1);
                mma_tf32(c[2 * jp],     ah0, ah1, ah2, ah3, bh0, bh1);
                mma_tf32(c[2 * jp + 1], ah0, ah1, ah2, ah3, bl2, bl3);
                mma_tf32(c[2 * jp + 1], al0, al1, al2, al3, bh2, bh3);
                mma_tf32(c[2 * jp + 1], ah0, ah1, ah2, ah3, bh2, bh3);
            }
            {
                uint32_t bh0, bh1, bl0, bl1;
                ldsm_x2(bh0, bh1, bH + 6 * 640 + s * 32);
                ldsm_x2(bl0, bl1, bL + 6 * 640 + s * 32);
                mma_tf32(c[6], ah0, ah1, ah2, ah3, bl0, bl1);
                mma_tf32(c[6], al0, al1, al2, al3, bh0, bh1);
                mma_tf32(c[6], ah0, ah1, ah2, ah3, bh0, bh1);
            }
        }

        if (kb + 1 < K1_CH) {
            sts_chunk(buf ^ 1);
            __syncthreads();
        }
    }
    __syncthreads();

    {
        const int g = lane >> 2;
        const int t = lane & 3;
        const int r1 = warp_m + g;
        const int r2 = r1 + 8;
#pragma unroll
        for (int j = 0; j < 7; j++) {
            const int col = warp_n + j * 8 + 2 * t;
            *(float2*)(E + r1 * K1_EPAD + col) =
                make_float2(c[j][0] * SMOOTH, c[j][1] * SMOOTH);
            *(float2*)(E + r2 * K1_EPAD + col) =
                make_float2(c[j][2] * SMOOTH, c[j][3] * SMOOTH);
        }
    }
    __syncthreads();

    for (int r = wid; r < K1_MT; r += 8) {
        float vals[7];
        float mx = -1e30f;
#pragma unroll
        for (int m = 0; m < 7; m++) {
            int cc = lane + 32 * m;
            vals[m] = (cc < NB) ? E[r * K1_EPAD + cc] : -1e30f;
            mx = fmaxf(mx, vals[m]);
        }
#pragma unroll
        for (int s = 16; s > 0; s >>= 1)
            mx = fmaxf(mx, __shfl_xor_sync(0xFFFFFFFFu, mx, s));
        float sum = 0.f;
#pragma unroll
        for (int m = 0; m < 7; m++) {
            float e = __expf(vals[m] - mx);
            vals[m] = e;
            sum += e;
        }
#pragma unroll
        for (int s = 16; s > 0; s >>= 1)
            sum += __shfl_xor_sync(0xFFFFFFFFu, sum, s);
        float inv = __frcp_rn(sum);
#pragma unroll
        for (int m = 0; m < 7; m++) {
            int cc = lane + 32 * m;
            if (cc < NB) E[r * K1_EPAD + cc] = vals[m] * inv;
        }
    }
    __syncthreads();

    if (tid < NB) {
        const int navalid = (NA - a0 < K1_MT) ? (NA - a0) : K1_MT;
        float* dst = g_attn + ((size_t)b * NB + tid) * NA + a0;
        for (int j = 0; j < navalid; j += 4) {
            float4 v;
            v.x = E[(j + 0) * K1_EPAD + tid];
            v.y = E[(j + 1) * K1_EPAD + tid];
            v.z = E[(j + 2) * K1_EPAD + tid];
            v.w = E[(j + 3) * K1_EPAD + tid];
            *(float4*)(dst + j) = v;
        }
    }
}

// ---------------------------------------------------------------------------
// Kernel 2 (mma.sync tf32, cp.async 6-stage deep pipeline + ldmatrix)
// ---------------------------------------------------------------------------
#define BM 128
#define BN 104
#define BK 16
#define KCH 13
#define APAD 20
#define G2_STAGES 6
#define G2_LOOKAHEAD 5
#define G2_AS   (BM * APAD)
#define G2_BS   (BN * APAD)
#define G2_BOFF (G2_STAGES * G2_AS)
#define G2_SMEM_BYTES ((G2_STAGES * (G2_AS + G2_BS)) * 4)   // 111360 B

__global__ __launch_bounds__(256, 2) void gemm2_mma_kernel(
    const float* __restrict__ VA,     // [B, DIM, NA]
    const float* __restrict__ VB,     // [B, DIM, NB]
    const float* __restrict__ gamma,  // [1]
    float* __restrict__ out)          // [B, DIM, NB]
{
    extern __shared__ __align__(16) float dsm[];
    float* AsBase = dsm;
    float* BsBase = dsm + G2_BOFF;

    const int tid  = threadIdx.x;
    const int wid  = tid >> 5;
    const int lane = tid & 31;

    const int b  = blockIdx.z;
    const int d0 = blockIdx.y * BM;
    const int n0 = blockIdx.x * BN;

    const float* Abase = VA + ((size_t)b * DIM + d0) * NA;
    const float* Bbase = g_attn + ((size_t)b * NB + n0) * NA;

    const int wrow = wid * 16;
    const int lm_hi = (lane >> 3) & 1;
    const int lm_q  = lane >> 4;
    const int lm_r  = lane & 7;
    const uint32_t smBase = smem_u32(dsm);
    const uint32_t a_off = (uint32_t)((wrow + lm_hi * 8 + lm_r) * APAD * 4 + lm_q * 16);
    const uint32_t b_off = (uint32_t)((lm_q * 8 + lm_r) * APAD * 4 + lm_hi * 16);

    float c[13][4];
#pragma unroll
    for (int j = 0; j < 13; j++)
#pragma unroll
        for (int i = 0; i < 4; i++) c[j][i] = 0.f;

    auto issue_chunk = [&](int kb) {
        const int slot = kb % G2_STAGES;
        const int kbase = kb * BK;
        float* sa = AsBase + slot * G2_AS;
        float* sb = BsBase + slot * G2_BS;
#pragma unroll
        for (int i = 0; i < 2; i++) {
            int idx = i * 256 + tid;
            int row = idx >> 2, c4 = idx & 3;
            int k = kbase + c4 * 4;
            bool p = (k < NA);
            const float* src = Abase + (size_t)row * NA + (p ? k : 0);
            cp_async16(smem_u32(sa + row * APAD + c4 * 4), src, p);
        }
#pragma unroll
        for (int i = 0; i < 2; i++) {
            int idx = i * 256 + tid;
            if (idx < BN * 4) {
                int row = idx >> 2, c4 = idx & 3;
                int k = kbase + c4 * 4;
                bool p = (k < NA) && (n0 + row < NB);
                const float* src = Bbase + (size_t)row * NA + (p ? k : 0);
                cp_async16(smem_u32(sb + row * APAD + c4 * 4), src, p);
            }
        }
        cp_commit();
    };

    // prologue: 5 chunks in flight
    issue_chunk(0);
    issue_chunk(1);
    issue_chunk(2);
    issue_chunk(3);
    issue_chunk(4);

    for (int kb = 0; kb < KCH; kb++) {
        cp_wait<G2_LOOKAHEAD - 1>();   // chunk kb's group complete
        __syncthreads();               // all warps finished kb-1 -> slot(kb+5)=slot(kb-1) reusable

        if (kb + G2_LOOKAHEAD < KCH) issue_chunk(kb + G2_LOOKAHEAD);
        else cp_commit();              // uniform group accounting

        const int slot = kb % G2_STAGES;
        const uint32_t aA = smBase + (slot * G2_AS) * 4 + a_off;
        const uint32_t bA = smBase + (G2_BOFF + slot * G2_BS) * 4 + b_off;

#pragma unroll
        for (int s = 0; s < 2; s++) {
            uint32_t a0, a1, a2, a3;
            ldsm_x4(a0, a1, a2, a3, aA + s * 32);
#pragma unroll
            for (int jp = 0; jp < 6; jp++) {
                uint32_t b0, b1, b2, b3;
                ldsm_x4(b0, b1, b2, b3, bA + jp * 1280 + s * 32);
                mma_tf32(c[2 * jp],     a0, a1, a2, a3, b0, b1);
                mma_tf32(c[2 * jp + 1], a0, a1, a2, a3, b2, b3);
            }
            {
                uint32_t b0, b1;
                ldsm_x2(b0, b1, bA + 12 * 640 + s * 32);
                mma_tf32(c[12], a0, a1, a2, a3, b0, b1);
            }
        }
    }

    const float gam = gamma[0];
    const int g = lane >> 2;
    const int t = lane & 3;
    const int row1 = d0 + wrow + g;
    const int row2 = row1 + 8;
#pragma unroll
    for (int j = 0; j < 13; j++) {
        int n = n0 + j * 8 + 2 * t;
        if (n < NB) {
            size_t i1 = ((size_t)b * DIM + row1) * NB + n;
            size_t i2 = ((size_t)b * DIM + row2) * NB + n;
            float2 vb1 = *(const float2*)(VB + i1);
            float2 vb2 = *(const float2*)(VB + i2);
            float2 r1 = make_float2(c[j][0] + vb1.x + gam, c[j][1] + vb1.y + gam);
            float2 r2 = make_float2(c[j][2] + vb2.x + gam, c[j][3] + vb2.y + gam);
            *(float2*)(out + i1) = r1;
            *(float2*)(out + i2) = r2;
        }
    }
}

// ---------------------------------------------------------------------------
extern "C" void kernel_launch(void* const* d_in, const int* in_sizes, int n_in,
                              void* d_out, int out_size) {
    const float* Q     = (const float*)d_in[0];  // query_a [B, NA, DK]
    const float* VA    = (const float*)d_in[1];  // value_a [B, DIM, NA]
    const float* KB    = (const float*)d_in[2];  // key_b   [B, DK, NB]
    const float* VB    = (const float*)d_in[3];  // value_b [B, DIM, NB]
    const float* gamma = (const float*)d_in[4];  // gamma   [1]
    float* out = (float*)d_out;

    cudaFuncSetAttribute(energy_softmax_mma_kernel,
                         cudaFuncAttributeMaxDynamicSharedMemorySize, K1_SMEM_BYTES);
    cudaFuncSetAttribute(gemm2_mma_kernel,
                         cudaFuncAttributeMaxDynamicSharedMemorySize, G2_SMEM_BYTES);

    dim3 g1((NA + K1_MT - 1) / K1_MT, B_);  // (7, 256)
    energy_softmax_mma_kernel<<<g1, 256, K1_SMEM_BYTES>>>(Q, KB);

    dim3 g2(2, DIM / BM, B_);               // (2, 8, 256)
    gemm2_mma_kernel<<<g2, 256, G2_SMEM_BYTES>>>(VA, VB, gamma, out);
}